// round 10
// baseline (speedup 1.0000x reference)
#include <cuda_runtime.h>

// YOLO loss, flat one-wave: grid (2,3,32) = 192 blocks x 512 threads.
// One thread = one float4 cls chunk (q = blockIdx.x*512+tid < 1000; m=q/20,
// chunk=q%20); chunk==0 thread also does GIoU. Deterministic fixed-point
// int64 accumulators; done-count and num_pos packed in one 64-bit word.
// Last-done block finalizes via atomicExch (read+reset in one RMW, no loads).

#define NPART 192
#define NTHREADS 512
#define FP_SCALE 4294967296.0   // 2^32

__device__ unsigned long long g_box_acc = 0ull;
__device__ unsigned long long g_cls_acc = 0ull;
__device__ unsigned long long g_done_np = 0ull;   // [63:32]=done count, [31:0]=np

__device__ __forceinline__ float warp_sum(float v) {
    #pragma unroll
    for (int o = 16; o > 0; o >>= 1) v += __shfl_down_sync(0xffffffffu, v, o);
    return v;
}

__global__ void __launch_bounds__(NTHREADS) yolo_flat(
    const float* __restrict__ box_preds,   // [32, 8400, 4]
    const float* __restrict__ cls_preds,   // [32, 8400, 80]
    const float* __restrict__ gt_boxes,    // [32, 50, 4]
    const int*   __restrict__ gt_labels,   // [32, 50]
    const void*  __restrict__ gt_mask,     // [32, 50] bool (byte or int32 layout)
    float*       __restrict__ out)
{
    const int tid  = threadIdx.x;
    const int lane = tid & 31;
    const int wrp  = tid >> 5;
    const int lvl  = blockIdx.y;
    const int b    = blockIdx.z;
    const int q    = blockIdx.x * NTHREADS + tid;   // 0..1023, guard < 1000

    const int  W      = (lvl == 0) ? 80 : (lvl == 1) ? 40 : 20;
    const int  offset = (lvl == 0) ? 0  : (lvl == 1) ? 6400 : 8000;
    const float inv_s = (lvl == 0) ? 0.125f : (lvl == 1) ? 0.0625f : 0.03125f;

    const int m     = q / 20;          // 0..49 (guarded)
    const int chunk = q - m * 20;      // 0..19

    float cls_acc = 0.0f;
    float box_acc = 0.0f;
    bool  pos     = false;

    if (q < 1000) {
        const int gtoff = b * 50 + m;
        // independent loads issued up-front, incl. BOTH mask layouts
        const float4 gb = __ldg((const float4*)(gt_boxes + (size_t)gtoff * 4));
        const int lab = __ldg(gt_labels + gtoff);
        const int probe  = *(const int*)gt_mask;
        const int mk_i32 = ((const int*)gt_mask)[gtoff];
        const int mk_u8  = (int)((const unsigned char*)gt_mask)[gtoff];
        const bool mk = (((unsigned)probe <= 1u) ? mk_i32 : mk_u8) != 0;

        const float x1 = gb.x, y1 = gb.y, x2 = gb.z, y2 = gb.w;
        const int gi = (int)floorf((x1 + x2) * 0.5f * inv_s);
        const int gj = (int)floorf((y1 + y2) * 0.5f * inv_s);
        const bool valid = mk && (gi >= 0) && (gj >= 0) && (gi < W) && (gj < W);
        const int idx = valid ? (offset + gj * W + gi) : 0;

        if (valid) {
            const size_t row = (size_t)b * 8400 + idx;
            const float4 xv = __ldg((const float4*)(cls_preds + row * 80 + chunk * 4));
            const int c4 = chunk * 4;
            const float xs[4] = {xv.x, xv.y, xv.z, xv.w};
            #pragma unroll
            for (int k = 0; k < 4; k++) {
                const float x = xs[k];
                const float e = __expf(-x);
                const float inv = 1.0f / (1.0f + e);
                const float L = __logf(1.0f + e);        // softplus(-x)
                if (c4 + k == lab) {
                    const float qq = e * inv;            // 1 - sigmoid(x)
                    cls_acc += 0.25f * qq * qq * L;
                } else {
                    const float p = inv;                 // sigmoid(x)
                    cls_acc += 0.75f * p * p * (x + L);  // softplus(x)
                }
            }

            if (chunk == 0) {
                pos = true;
                const float4 pbv = __ldg((const float4*)(box_preds + row * 4));
                const float px1 = pbv.x, py1 = pbv.y, px2 = pbv.z, py2 = pbv.w;
                const float ix1 = fmaxf(px1, x1), iy1 = fmaxf(py1, y1);
                const float ix2 = fminf(px2, x2), iy2 = fminf(py2, y2);
                const float inter = fmaxf(ix2 - ix1, 0.0f) * fmaxf(iy2 - iy1, 0.0f);
                const float a1 = (px2 - px1) * (py2 - py1);
                const float a2 = (x2 - x1) * (y2 - y1);
                const float uni = a1 + a2 - inter;
                const float iou = inter / uni;
                const float ex1 = fminf(px1, x1), ey1 = fminf(py1, y1);
                const float ex2 = fmaxf(px2, x2), ey2 = fmaxf(py2, y2);
                const float encl = (ex2 - ex1) * (ey2 - ey1);
                box_acc = 1.0f - (iou - (encl - uni) / encl);
            }
        }
    }

    // Block reduction: warp sums -> smem[16] -> thread 0
    __shared__ float w0[16], w1[16];
    __shared__ int   w2[16];
    const float rb = warp_sum(box_acc);
    const float rc = warp_sum(cls_acc);
    const int   rn = __popc(__ballot_sync(0xffffffffu, pos));
    if (lane == 0) { w0[wrp] = rb; w1[wrp] = rc; w2[wrp] = rn; }
    __syncthreads();

    if (tid == 0) {
        float vb = 0.0f, vc = 0.0f; int vn = 0;
        #pragma unroll
        for (int i = 0; i < 16; i++) { vb += w0[i]; vc += w1[i]; vn += w2[i]; }
        // deterministic fixed-point accumulation (integer add is associative)
        const long long qb = __double2ll_rn((double)vb * FP_SCALE);
        const long long qc = __double2ll_rn((double)vc * FP_SCALE);
        atomicAdd(&g_box_acc, (unsigned long long)qb);
        atomicAdd(&g_cls_acc, (unsigned long long)qc);
        __threadfence();   // release: sums visible before done-count arrival
        const unsigned long long pack = (1ull << 32) | (unsigned long long)(unsigned)vn;
        const unsigned long long ret = atomicAdd(&g_done_np, pack);
        if ((unsigned)(ret >> 32) == NPART - 1) {
            __threadfence();   // acquire: observe all blocks' accumulator adds
            // read + reset in one RMW each (no separate loads/stores)
            const long long sb = (long long)atomicExch(&g_box_acc, 0ull);
            const long long sc = (long long)atomicExch(&g_cls_acc, 0ull);
            const long long sn = (long long)(unsigned)(ret & 0xffffffffull) + vn;
            const double denom = (double)(sn > 1 ? sn : 1);
            out[0] = (float)((5.0 * (double)sb * (1.0 / FP_SCALE)
                                  + (double)sc * (1.0 / FP_SCALE)) / denom);
            g_done_np = 0ull;   // all blocks done; visible by next launch
        }
    }
}

extern "C" void kernel_launch(void* const* d_in, const int* in_sizes, int n_in,
                              void* d_out, int out_size)
{
    const float* box_preds = (const float*)d_in[0];
    const float* cls_preds = (const float*)d_in[1];
    const float* gt_boxes  = (const float*)d_in[2];
    const int*   gt_labels = (const int*)d_in[3];
    const void*  gt_mask   = d_in[4];
    float* out = (float*)d_out;

    dim3 grid(2, 3, 32);
    yolo_flat<<<grid, NTHREADS>>>(box_preds, cls_preds, gt_boxes, gt_labels, gt_mask, out);
}

// round 12
// speedup vs baseline: 1.1007x; 1.1007x over previous
#include <cuda_runtime.h>

// YOLO loss, flat one-wave (R5 structure): grid (4,3,32) = 384 blocks x 256.
// One thread = one float4 cls chunk (q = blockIdx.x*256+tid < 1000; m=q/20,
// chunk=q%20); chunk==0 thread also does GIoU.
// Tail: packed (box,cls) partial per block as one 64-bit word; np packed into
// done-counter low bits; last-done block gathers 384 words and finalizes.

#define NPART 384
#define NTHREADS 256

__device__ unsigned long long g_part[NPART];     // [31:0]=box bits, [63:32]=cls bits
__device__ unsigned long long g_done_np = 0ull;  // [63:32]=done count, [31:0]=np

__device__ __forceinline__ float warp_sum(float v) {
    #pragma unroll
    for (int o = 16; o > 0; o >>= 1) v += __shfl_down_sync(0xffffffffu, v, o);
    return v;
}

__global__ void __launch_bounds__(NTHREADS) yolo_flat(
    const float* __restrict__ box_preds,   // [32, 8400, 4]
    const float* __restrict__ cls_preds,   // [32, 8400, 80]
    const float* __restrict__ gt_boxes,    // [32, 50, 4]
    const int*   __restrict__ gt_labels,   // [32, 50]
    const void*  __restrict__ gt_mask,     // [32, 50] bool (byte or int32 layout)
    float*       __restrict__ out)
{
    const int tid  = threadIdx.x;
    const int lane = tid & 31;
    const int wrp  = tid >> 5;
    const int lvl  = blockIdx.y;
    const int b    = blockIdx.z;
    const int q    = blockIdx.x * NTHREADS + tid;   // 0..1023, guard < 1000

    const int  W      = (lvl == 0) ? 80 : (lvl == 1) ? 40 : 20;
    const int  offset = (lvl == 0) ? 0  : (lvl == 1) ? 6400 : 8000;
    const float inv_s = (lvl == 0) ? 0.125f : (lvl == 1) ? 0.0625f : 0.03125f;

    const int m     = q / 20;          // 0..49
    const int chunk = q - m * 20;      // 0..19

    float cls_acc = 0.0f;
    float box_acc = 0.0f;
    bool  pos     = false;

    if (q < 1000) {
        const int gtoff = b * 50 + m;
        const float4 gb = __ldg((const float4*)(gt_boxes + (size_t)gtoff * 4));
        const int lab = __ldg(gt_labels + gtoff);

        bool mk;
        {
            const int first = *(const int*)gt_mask;   // broadcast dtype probe
            if ((unsigned)first <= 1u)
                mk = ((const int*)gt_mask)[gtoff] != 0;
            else
                mk = ((const unsigned char*)gt_mask)[gtoff] != 0;
        }

        const float x1 = gb.x, y1 = gb.y, x2 = gb.z, y2 = gb.w;
        const int gi = (int)floorf((x1 + x2) * 0.5f * inv_s);
        const int gj = (int)floorf((y1 + y2) * 0.5f * inv_s);
        const bool valid = mk && (gi >= 0) && (gj >= 0) && (gi < W) && (gj < W);
        const int idx = valid ? (offset + gj * W + gi) : 0;

        if (valid) {
            const size_t row = (size_t)b * 8400 + idx;
            const float4 xv = __ldg((const float4*)(cls_preds + row * 80 + chunk * 4));
            const int c4 = chunk * 4;
            const float xs[4] = {xv.x, xv.y, xv.z, xv.w};
            #pragma unroll
            for (int k = 0; k < 4; k++) {
                const float x = xs[k];
                const float e = __expf(-x);
                const float inv = 1.0f / (1.0f + e);
                const float L = __logf(1.0f + e);        // softplus(-x)
                if (c4 + k == lab) {
                    const float qq = e * inv;            // 1 - sigmoid(x)
                    cls_acc += 0.25f * qq * qq * L;
                } else {
                    const float p = inv;                 // sigmoid(x)
                    cls_acc += 0.75f * p * p * (x + L);  // softplus(x)
                }
            }

            if (chunk == 0) {
                pos = true;
                const float4 pbv = __ldg((const float4*)(box_preds + row * 4));
                const float px1 = pbv.x, py1 = pbv.y, px2 = pbv.z, py2 = pbv.w;
                const float ix1 = fmaxf(px1, x1), iy1 = fmaxf(py1, y1);
                const float ix2 = fminf(px2, x2), iy2 = fminf(py2, y2);
                const float inter = fmaxf(ix2 - ix1, 0.0f) * fmaxf(iy2 - iy1, 0.0f);
                const float a1 = (px2 - px1) * (py2 - py1);
                const float a2 = (x2 - x1) * (y2 - y1);
                const float uni = a1 + a2 - inter;
                const float iou = inter / uni;
                const float ex1 = fminf(px1, x1), ey1 = fminf(py1, y1);
                const float ex2 = fmaxf(px2, x2), ey2 = fmaxf(py2, y2);
                const float encl = (ex2 - ex1) * (ey2 - ey1);
                box_acc = 1.0f - (iou - (encl - uni) / encl);
            }
        }
    }

    // Block reduction: warp sums -> smem[8] -> warp 0
    __shared__ float w0[8], w1[8];
    __shared__ int   w2[8];
    const float rb = warp_sum(box_acc);
    const float rc = warp_sum(cls_acc);
    const int   rn = __popc(__ballot_sync(0xffffffffu, pos));
    if (lane == 0) { w0[wrp] = rb; w1[wrp] = rc; w2[wrp] = rn; }
    __syncthreads();

    const int blk = (b * 3 + lvl) * 4 + blockIdx.x;   // 0..383
    __shared__ bool s_last;
    __shared__ int  s_np;
    if (tid == 0) {
        float vb = 0.0f, vc = 0.0f; int vn = 0;
        #pragma unroll
        for (int i = 0; i < 8; i++) { vb += w0[i]; vc += w1[i]; vn += w2[i]; }
        const unsigned long long packed =
            (unsigned long long)__float_as_uint(vb) |
            ((unsigned long long)__float_as_uint(vc) << 32);
        g_part[blk] = packed;                          // one STG.64
        __threadfence();                               // release partial
        const unsigned long long pack =
            (1ull << 32) | (unsigned long long)(unsigned)vn;
        const unsigned long long ret = atomicAdd(&g_done_np, pack);
        s_last = ((unsigned)(ret >> 32) == NPART - 1);
        s_np   = (int)(unsigned)(ret & 0xffffffffull) + vn;
    }
    __syncthreads();

    if (s_last) {
        // gather 384 packed partials: <=2 64-bit loads per thread
        unsigned long long p0 = *((volatile unsigned long long*)&g_part[tid]);
        float vb = __uint_as_float((unsigned)(p0 & 0xffffffffull));
        float vc = __uint_as_float((unsigned)(p0 >> 32));
        if (tid < NPART - NTHREADS) {
            unsigned long long p1 =
                *((volatile unsigned long long*)&g_part[tid + NTHREADS]);
            vb += __uint_as_float((unsigned)(p1 & 0xffffffffull));
            vc += __uint_as_float((unsigned)(p1 >> 32));
        }
        vb = warp_sum(vb); vc = warp_sum(vc);
        if (lane == 0) { w0[wrp] = vb; w1[wrp] = vc; }
        __syncthreads();
        if (tid == 0) {
            float sb = 0.0f, sc = 0.0f;
            #pragma unroll
            for (int i = 0; i < 8; i++) { sb += w0[i]; sc += w1[i]; }
            const int sn = s_np;
            const float denom = (float)(sn > 1 ? sn : 1);
            out[0] = (5.0f * sb + sc) / denom;
            g_done_np = 0ull;   // reset for next graph replay
        }
    }
}

extern "C" void kernel_launch(void* const* d_in, const int* in_sizes, int n_in,
                              void* d_out, int out_size)
{
    const float* box_preds = (const float*)d_in[0];
    const float* cls_preds = (const float*)d_in[1];
    const float* gt_boxes  = (const float*)d_in[2];
    const int*   gt_labels = (const int*)d_in[3];
    const void*  gt_mask   = d_in[4];
    float* out = (float*)d_out;

    dim3 grid(4, 3, 32);
    yolo_flat<<<grid, NTHREADS>>>(box_preds, cls_preds, gt_boxes, gt_labels, gt_mask, out);
}

// round 13
// speedup vs baseline: 1.1250x; 1.0221x over previous
#include <cuda_runtime.h>

// YOLO loss, flat one-wave: grid (8,3,32) = 768 blocks x 128 threads.
// One thread = one float4 cls chunk (q = blockIdx.x*128+tid < 1000; m=q/20,
// chunk=q%20); chunk==0 thread also does GIoU.
// Tail: packed (box,cls) 64-bit partial per block; np packed into done-counter
// low bits; last-done block gathers 768 words (6 per thread) and finalizes.

#define NPART 768
#define NTHREADS 128

__device__ unsigned long long g_part[NPART];     // [31:0]=box bits, [63:32]=cls bits
__device__ unsigned long long g_done_np = 0ull;  // [63:32]=done count, [31:0]=np

__device__ __forceinline__ float warp_sum(float v) {
    #pragma unroll
    for (int o = 16; o > 0; o >>= 1) v += __shfl_down_sync(0xffffffffu, v, o);
    return v;
}

__global__ void __launch_bounds__(NTHREADS) yolo_flat(
    const float* __restrict__ box_preds,   // [32, 8400, 4]
    const float* __restrict__ cls_preds,   // [32, 8400, 80]
    const float* __restrict__ gt_boxes,    // [32, 50, 4]
    const int*   __restrict__ gt_labels,   // [32, 50]
    const void*  __restrict__ gt_mask,     // [32, 50] bool (byte or int32 layout)
    float*       __restrict__ out)
{
    const int tid  = threadIdx.x;
    const int lane = tid & 31;
    const int wrp  = tid >> 5;
    const int lvl  = blockIdx.y;
    const int b    = blockIdx.z;
    const int q    = blockIdx.x * NTHREADS + tid;   // 0..1023, guard < 1000

    const int  W      = (lvl == 0) ? 80 : (lvl == 1) ? 40 : 20;
    const int  offset = (lvl == 0) ? 0  : (lvl == 1) ? 6400 : 8000;
    const float inv_s = (lvl == 0) ? 0.125f : (lvl == 1) ? 0.0625f : 0.03125f;

    const int m     = q / 20;          // 0..49
    const int chunk = q - m * 20;      // 0..19

    float cls_acc = 0.0f;
    float box_acc = 0.0f;
    bool  pos     = false;

    if (q < 1000) {
        const int gtoff = b * 50 + m;
        const float4 gb = __ldg((const float4*)(gt_boxes + (size_t)gtoff * 4));
        const int lab = __ldg(gt_labels + gtoff);

        bool mk;
        {
            const int first = *(const int*)gt_mask;   // broadcast dtype probe
            if ((unsigned)first <= 1u)
                mk = ((const int*)gt_mask)[gtoff] != 0;
            else
                mk = ((const unsigned char*)gt_mask)[gtoff] != 0;
        }

        const float x1 = gb.x, y1 = gb.y, x2 = gb.z, y2 = gb.w;
        const int gi = (int)floorf((x1 + x2) * 0.5f * inv_s);
        const int gj = (int)floorf((y1 + y2) * 0.5f * inv_s);
        const bool valid = mk && (gi >= 0) && (gj >= 0) && (gi < W) && (gj < W);
        const int idx = valid ? (offset + gj * W + gi) : 0;

        if (valid) {
            const size_t row = (size_t)b * 8400 + idx;
            const float4 xv = __ldg((const float4*)(cls_preds + row * 80 + chunk * 4));
            const int c4 = chunk * 4;
            const float xs[4] = {xv.x, xv.y, xv.z, xv.w};
            #pragma unroll
            for (int k = 0; k < 4; k++) {
                const float x = xs[k];
                const float e = __expf(-x);
                const float inv = 1.0f / (1.0f + e);
                const float L = __logf(1.0f + e);        // softplus(-x)
                if (c4 + k == lab) {
                    const float qq = e * inv;            // 1 - sigmoid(x)
                    cls_acc += 0.25f * qq * qq * L;
                } else {
                    const float p = inv;                 // sigmoid(x)
                    cls_acc += 0.75f * p * p * (x + L);  // softplus(x)
                }
            }

            if (chunk == 0) {
                pos = true;
                const float4 pbv = __ldg((const float4*)(box_preds + row * 4));
                const float px1 = pbv.x, py1 = pbv.y, px2 = pbv.z, py2 = pbv.w;
                const float ix1 = fmaxf(px1, x1), iy1 = fmaxf(py1, y1);
                const float ix2 = fminf(px2, x2), iy2 = fminf(py2, y2);
                const float inter = fmaxf(ix2 - ix1, 0.0f) * fmaxf(iy2 - iy1, 0.0f);
                const float a1 = (px2 - px1) * (py2 - py1);
                const float a2 = (x2 - x1) * (y2 - y1);
                const float uni = a1 + a2 - inter;
                const float iou = inter / uni;
                const float ex1 = fminf(px1, x1), ey1 = fminf(py1, y1);
                const float ex2 = fmaxf(px2, x2), ey2 = fmaxf(py2, y2);
                const float encl = (ex2 - ex1) * (ey2 - ey1);
                box_acc = 1.0f - (iou - (encl - uni) / encl);
            }
        }
    }

    // Block reduction: warp sums -> smem[4] -> thread 0
    __shared__ float w0[4], w1[4];
    __shared__ int   w2[4];
    const float rb = warp_sum(box_acc);
    const float rc = warp_sum(cls_acc);
    const int   rn = __popc(__ballot_sync(0xffffffffu, pos));
    if (lane == 0) { w0[wrp] = rb; w1[wrp] = rc; w2[wrp] = rn; }
    __syncthreads();

    const int blk = (b * 3 + lvl) * 8 + blockIdx.x;   // 0..767
    __shared__ bool s_last;
    __shared__ int  s_np;
    if (tid == 0) {
        float vb = 0.0f, vc = 0.0f; int vn = 0;
        #pragma unroll
        for (int i = 0; i < 4; i++) { vb += w0[i]; vc += w1[i]; vn += w2[i]; }
        const unsigned long long packed =
            (unsigned long long)__float_as_uint(vb) |
            ((unsigned long long)__float_as_uint(vc) << 32);
        g_part[blk] = packed;                          // one STG.64
        __threadfence();                               // release partial
        const unsigned long long pack =
            (1ull << 32) | (unsigned long long)(unsigned)vn;
        const unsigned long long ret = atomicAdd(&g_done_np, pack);
        s_last = ((unsigned)(ret >> 32) == NPART - 1);
        s_np   = (int)(unsigned)(ret & 0xffffffffull) + vn;
    }
    __syncthreads();

    if (s_last) {
        // gather 768 packed partials: 6 independent 64-bit loads per thread
        float vb = 0.0f, vc = 0.0f;
        #pragma unroll
        for (int i = 0; i < NPART / NTHREADS; i++) {
            const unsigned long long p =
                *((volatile unsigned long long*)&g_part[tid + i * NTHREADS]);
            vb += __uint_as_float((unsigned)(p & 0xffffffffull));
            vc += __uint_as_float((unsigned)(p >> 32));
        }
        vb = warp_sum(vb); vc = warp_sum(vc);
        if (lane == 0) { w0[wrp] = vb; w1[wrp] = vc; }
        __syncthreads();
        if (tid == 0) {
            float sb = 0.0f, sc = 0.0f;
            #pragma unroll
            for (int i = 0; i < 4; i++) { sb += w0[i]; sc += w1[i]; }
            const int sn = s_np;
            const float denom = (float)(sn > 1 ? sn : 1);
            out[0] = (5.0f * sb + sc) / denom;
            g_done_np = 0ull;   // reset for next graph replay
        }
    }
}

extern "C" void kernel_launch(void* const* d_in, const int* in_sizes, int n_in,
                              void* d_out, int out_size)
{
    const float* box_preds = (const float*)d_in[0];
    const float* cls_preds = (const float*)d_in[1];
    const float* gt_boxes  = (const float*)d_in[2];
    const int*   gt_labels = (const int*)d_in[3];
    const void*  gt_mask   = d_in[4];
    float* out = (float*)d_out;

    dim3 grid(8, 3, 32);
    yolo_flat<<<grid, NTHREADS>>>(box_preds, cls_preds, gt_boxes, gt_labels, gt_mask, out);
}